// round 1
// baseline (speedup 1.0000x reference)
#include <cuda_runtime.h>
#include <cuda_bf16.h>
#include <math.h>

// Shapes (fixed by the problem)
#define BATCH 8
#define SEQ   1024
#define DMODEL 1024
#define NHEAD 16
#define HD    64
#define FFDIM 4096
#define MROWS (BATCH*SEQ)   // 8192

// ---------------- scratch (device globals; no allocation allowed) ----------
__device__ float g_xn [MROWS*DMODEL];
__device__ float g_q  [MROWS*DMODEL];
__device__ float g_k  [MROWS*DMODEL];
__device__ float g_v  [MROWS*DMODEL];
__device__ float g_ctx[MROWS*DMODEL];
__device__ float g_y1 [MROWS*DMODEL];
__device__ float g_ff [MROWS*FFDIM];

// ---------------- helpers ----------------
__device__ __forceinline__ unsigned f2tf(float x) {
    unsigned u;
    asm("cvt.rna.tf32.f32 %0, %1;" : "=r"(u) : "f"(x));
    return u;
}
__device__ __forceinline__ float f2tf_f(float x) { return __uint_as_float(f2tf(x)); }

__device__ __forceinline__ void mma8(float acc[4], const unsigned a[4],
                                     unsigned b0, unsigned b1) {
    asm volatile(
        "mma.sync.aligned.m16n8k8.row.col.f32.tf32.tf32.f32 "
        "{%0,%1,%2,%3}, {%4,%5,%6,%7}, {%8,%9}, {%0,%1,%2,%3};\n"
        : "+f"(acc[0]), "+f"(acc[1]), "+f"(acc[2]), "+f"(acc[3])
        : "r"(a[0]), "r"(a[1]), "r"(a[2]), "r"(a[3]), "r"(b0), "r"(b1));
}

// Block-wide sum, broadcast to all threads. Safe to call repeatedly.
__device__ __forceinline__ float block_sum(float v) {
    __shared__ float sh[32];
    int tid = threadIdx.x;
    #pragma unroll
    for (int o = 16; o; o >>= 1) v += __shfl_xor_sync(0xffffffffu, v, o);
    __syncthreads();
    if ((tid & 31) == 0) sh[tid >> 5] = v;
    __syncthreads();
    if (tid < 32) {
        float t = (tid < (int)(blockDim.x >> 5)) ? sh[tid] : 0.f;
        #pragma unroll
        for (int o = 4; o; o >>= 1) t += __shfl_xor_sync(0xffffffffu, t, o);
        if (tid == 0) sh[0] = t;
    }
    __syncthreads();
    return sh[0];
}

// ---------------- LayerNorm kernels (D = 1024, 256 threads, 4 elems/thread) ----
__global__ void ln_double_kernel(const float* __restrict__ X,
                                 const float* __restrict__ g1, const float* __restrict__ b1,
                                 const float* __restrict__ g2, const float* __restrict__ b2,
                                 float* __restrict__ Y) {
    int row = blockIdx.x, tid = threadIdx.x;
    float4 v = ((const float4*)X)[(size_t)row * 256 + tid];
    float mu = block_sum(v.x + v.y + v.z + v.w) * (1.0f / 1024.0f);
    float d0 = v.x - mu, d1 = v.y - mu, d2 = v.z - mu, d3 = v.w - mu;
    float var = block_sum(d0*d0 + d1*d1 + d2*d2 + d3*d3) * (1.0f / 1024.0f);
    float inv = rsqrtf(var + 1e-6f);
    float4 G = ((const float4*)g1)[tid], Bv = ((const float4*)b1)[tid];
    float y0 = d0*inv*G.x + Bv.x, y1 = d1*inv*G.y + Bv.y;
    float y2 = d2*inv*G.z + Bv.z, y3 = d3*inv*G.w + Bv.w;
    // second LN
    float mu2 = block_sum(y0 + y1 + y2 + y3) * (1.0f / 1024.0f);
    float e0 = y0 - mu2, e1 = y1 - mu2, e2 = y2 - mu2, e3 = y3 - mu2;
    float var2 = block_sum(e0*e0 + e1*e1 + e2*e2 + e3*e3) * (1.0f / 1024.0f);
    float inv2 = rsqrtf(var2 + 1e-6f);
    float4 G2 = ((const float4*)g2)[tid], B2 = ((const float4*)b2)[tid];
    float4 o;
    o.x = e0*inv2*G2.x + B2.x; o.y = e1*inv2*G2.y + B2.y;
    o.z = e2*inv2*G2.z + B2.z; o.w = e3*inv2*G2.w + B2.w;
    ((float4*)Y)[(size_t)row * 256 + tid] = o;
}

__global__ void ln_single_kernel(const float* __restrict__ X,
                                 const float* __restrict__ g, const float* __restrict__ b,
                                 float* __restrict__ Y) {
    int row = blockIdx.x, tid = threadIdx.x;
    float4 v = ((const float4*)X)[(size_t)row * 256 + tid];
    float mu = block_sum(v.x + v.y + v.z + v.w) * (1.0f / 1024.0f);
    float d0 = v.x - mu, d1 = v.y - mu, d2 = v.z - mu, d3 = v.w - mu;
    float var = block_sum(d0*d0 + d1*d1 + d2*d2 + d3*d3) * (1.0f / 1024.0f);
    float inv = rsqrtf(var + 1e-6f);
    float4 G = ((const float4*)g)[tid], Bv = ((const float4*)b)[tid];
    float4 o;
    o.x = d0*inv*G.x + Bv.x; o.y = d1*inv*G.y + Bv.y;
    o.z = d2*inv*G.z + Bv.z; o.w = d3*inv*G.w + Bv.w;
    ((float4*)Y)[(size_t)row * 256 + tid] = o;
}

// ---------------- TF32 GEMM: C[M,N] = A[M,K] @ W[K,N] + bias (+gelu) (+res) ----
// BM=128, BN=128, BK=32, 256 threads, warp tile 64x32.
// act: 0 = none, 1 = exact GELU. res: optional residual added pre-store.
__global__ __launch_bounds__(256, 2) void gemm_tf32_kernel(
    const float* __restrict__ A, const float* __restrict__ W,
    const float* __restrict__ bias, const float* __restrict__ res,
    float* __restrict__ C, int M, int N, int K, int act) {
    __shared__ float As[128][36];
    __shared__ float Bs[32][132];
    int tid = threadIdx.x;
    int lane = tid & 31, warp = tid >> 5;
    int g = lane >> 2, c4 = lane & 3;
    int wm = (warp >> 2) * 64;
    int wn = (warp & 3) * 32;
    int m0 = blockIdx.y * 128, n0 = blockIdx.x * 128;

    float acc[4][4][4] = {};

    for (int k0 = 0; k0 < K; k0 += 32) {
        __syncthreads();
        #pragma unroll
        for (int i = 0; i < 4; i++) {
            int c = tid + i * 256;
            int r = c >> 3, cg = c & 7;
            float4 v = *(const float4*)(A + (size_t)(m0 + r) * K + k0 + cg * 4);
            float4 t;
            t.x = f2tf_f(v.x); t.y = f2tf_f(v.y); t.z = f2tf_f(v.z); t.w = f2tf_f(v.w);
            *(float4*)&As[r][cg * 4] = t;
        }
        #pragma unroll
        for (int i = 0; i < 4; i++) {
            int c = tid + i * 256;
            int kr = c >> 5, nc = c & 31;
            float4 v = *(const float4*)(W + (size_t)(k0 + kr) * N + n0 + nc * 4);
            float4 t;
            t.x = f2tf_f(v.x); t.y = f2tf_f(v.y); t.z = f2tf_f(v.z); t.w = f2tf_f(v.w);
            *(float4*)&Bs[kr][nc * 4] = t;
        }
        __syncthreads();
        #pragma unroll
        for (int ks = 0; ks < 32; ks += 8) {
            unsigned a[4][4], b[4][2];
            #pragma unroll
            for (int mi = 0; mi < 4; mi++) {
                int r = wm + mi * 16 + g;
                a[mi][0] = __float_as_uint(As[r][ks + c4]);
                a[mi][1] = __float_as_uint(As[r + 8][ks + c4]);
                a[mi][2] = __float_as_uint(As[r][ks + c4 + 4]);
                a[mi][3] = __float_as_uint(As[r + 8][ks + c4 + 4]);
            }
            #pragma unroll
            for (int ni = 0; ni < 4; ni++) {
                int cn = wn + ni * 8 + g;
                b[ni][0] = __float_as_uint(Bs[ks + c4][cn]);
                b[ni][1] = __float_as_uint(Bs[ks + c4 + 4][cn]);
            }
            #pragma unroll
            for (int mi = 0; mi < 4; mi++)
                #pragma unroll
                for (int ni = 0; ni < 4; ni++)
                    mma8(acc[mi][ni], a[mi], b[ni][0], b[ni][1]);
        }
    }

    // epilogue
    #pragma unroll
    for (int mi = 0; mi < 4; mi++) {
        #pragma unroll
        for (int ni = 0; ni < 4; ni++) {
            int r = wm + mi * 16 + g;
            int cn = wn + ni * 8 + c4 * 2;
            int gn = n0 + cn;
            float bv0 = bias[gn], bv1 = bias[gn + 1];
            #pragma unroll
            for (int half = 0; half < 2; half++) {
                int gr = m0 + r + half * 8;
                float v0 = acc[mi][ni][half * 2 + 0] + bv0;
                float v1 = acc[mi][ni][half * 2 + 1] + bv1;
                if (act == 1) {
                    v0 = 0.5f * v0 * (1.0f + erff(v0 * 0.70710678118654752f));
                    v1 = 0.5f * v1 * (1.0f + erff(v1 * 0.70710678118654752f));
                }
                size_t o = (size_t)gr * N + gn;
                if (res) { v0 += res[o]; v1 += res[o + 1]; }
                C[o] = v0; C[o + 1] = v1;
            }
        }
    }
}

// ---------------- Flash attention (TF32 MMA), HD=64 --------------------------
// grid: (B*H, S/64). block: 128 threads (4 warps), each warp owns 16 q rows.
#define APAD 68
#define ATTN_SMEM (3 * 64 * APAD * 4)

__global__ __launch_bounds__(128) void attn_kernel(
    const float* __restrict__ Q, const float* __restrict__ Kb,
    const float* __restrict__ Vb, float* __restrict__ O) {
    extern __shared__ float sm[];
    float* Ks = sm;                 // [64][APAD]
    float* Vs = sm + 64 * APAD;     // [64][APAD]
    float* Ps = sm + 2 * 64 * APAD; // [64][APAD]

    int tid = threadIdx.x, lane = tid & 31, warp = tid >> 5;
    int g = lane >> 2, c4 = lane & 3;
    int bh = blockIdx.x, qt = blockIdx.y;
    int b = bh >> 4, h = bh & 15;

    // load Q fragments (scaled by 1/sqrt(HD) = 0.125)
    unsigned aQ[8][4];
    {
        int qr = qt * 64 + warp * 16 + g;
        const float* q0 = Q + ((size_t)(b * SEQ + qr)) * DMODEL + h * HD;
        const float* q8 = q0 + (size_t)8 * DMODEL;
        #pragma unroll
        for (int ks = 0; ks < 8; ks++) {
            int col = ks * 8 + c4;
            aQ[ks][0] = f2tf(q0[col] * 0.125f);
            aQ[ks][1] = f2tf(q8[col] * 0.125f);
            aQ[ks][2] = f2tf(q0[col + 4] * 0.125f);
            aQ[ks][3] = f2tf(q8[col + 4] * 0.125f);
        }
    }

    float m0 = -INFINITY, m1 = -INFINITY, l0 = 0.f, l1 = 0.f;
    float acc[8][4] = {};

    for (int kt = 0; kt < SEQ / 64; kt++) {
        __syncthreads();
        #pragma unroll
        for (int i = 0; i < 8; i++) {
            int cidx = tid + i * 128;
            int kr = cidx >> 4, h4 = cidx & 15;
            size_t goff = ((size_t)(b * SEQ + kt * 64 + kr)) * DMODEL + h * HD + h4 * 4;
            float4 kv = *(const float4*)(Kb + goff);
            float4 vv = *(const float4*)(Vb + goff);
            float* kd = &Ks[kr * APAD + h4 * 4];
            kd[0] = f2tf_f(kv.x); kd[1] = f2tf_f(kv.y);
            kd[2] = f2tf_f(kv.z); kd[3] = f2tf_f(kv.w);
            float* vd = &Vs[kr * APAD + h4 * 4];
            vd[0] = f2tf_f(vv.x); vd[1] = f2tf_f(vv.y);
            vd[2] = f2tf_f(vv.z); vd[3] = f2tf_f(vv.w);
        }
        __syncthreads();

        // scores: S = Q @ K^T  (16 x 64 per warp)
        float s[8][4] = {};
        #pragma unroll
        for (int ks = 0; ks < 8; ks++) {
            #pragma unroll
            for (int nt = 0; nt < 8; nt++) {
                unsigned b0 = __float_as_uint(Ks[(nt * 8 + g) * APAD + ks * 8 + c4]);
                unsigned b1 = __float_as_uint(Ks[(nt * 8 + g) * APAD + ks * 8 + c4 + 4]);
                mma8(s[nt], aQ[ks], b0, b1);
            }
        }

        // online softmax
        float tm0 = -INFINITY, tm1 = -INFINITY;
        #pragma unroll
        for (int nt = 0; nt < 8; nt++) {
            tm0 = fmaxf(tm0, fmaxf(s[nt][0], s[nt][1]));
            tm1 = fmaxf(tm1, fmaxf(s[nt][2], s[nt][3]));
        }
        tm0 = fmaxf(tm0, __shfl_xor_sync(0xffffffffu, tm0, 1));
        tm0 = fmaxf(tm0, __shfl_xor_sync(0xffffffffu, tm0, 2));
        tm1 = fmaxf(tm1, __shfl_xor_sync(0xffffffffu, tm1, 1));
        tm1 = fmaxf(tm1, __shfl_xor_sync(0xffffffffu, tm1, 2));
        float mn0 = fmaxf(m0, tm0), mn1 = fmaxf(m1, tm1);
        float cf0 = __expf(m0 - mn0), cf1 = __expf(m1 - mn1);
        m0 = mn0; m1 = mn1;

        float rs0 = 0.f, rs1 = 0.f;
        int pr = warp * 16 + g;
        #pragma unroll
        for (int nt = 0; nt < 8; nt++) {
            float p0 = __expf(s[nt][0] - m0), p1 = __expf(s[nt][1] - m0);
            float p2 = __expf(s[nt][2] - m1), p3 = __expf(s[nt][3] - m1);
            rs0 += p0 + p1; rs1 += p2 + p3;
            int pc = nt * 8 + c4 * 2;
            Ps[pr * APAD + pc]       = f2tf_f(p0);
            Ps[pr * APAD + pc + 1]   = f2tf_f(p1);
            Ps[(pr + 8) * APAD + pc]     = f2tf_f(p2);
            Ps[(pr + 8) * APAD + pc + 1] = f2tf_f(p3);
        }
        rs0 += __shfl_xor_sync(0xffffffffu, rs0, 1);
        rs0 += __shfl_xor_sync(0xffffffffu, rs0, 2);
        rs1 += __shfl_xor_sync(0xffffffffu, rs1, 1);
        rs1 += __shfl_xor_sync(0xffffffffu, rs1, 2);
        l0 = l0 * cf0 + rs0; l1 = l1 * cf1 + rs1;
        #pragma unroll
        for (int nt = 0; nt < 8; nt++) {
            acc[nt][0] *= cf0; acc[nt][1] *= cf0;
            acc[nt][2] *= cf1; acc[nt][3] *= cf1;
        }
        __syncwarp();

        // acc += P @ V
        #pragma unroll
        for (int ks = 0; ks < 8; ks++) {
            unsigned a[4];
            a[0] = __float_as_uint(Ps[(warp * 16 + g) * APAD + ks * 8 + c4]);
            a[1] = __float_as_uint(Ps[(warp * 16 + g + 8) * APAD + ks * 8 + c4]);
            a[2] = __float_as_uint(Ps[(warp * 16 + g) * APAD + ks * 8 + c4 + 4]);
            a[3] = __float_as_uint(Ps[(warp * 16 + g + 8) * APAD + ks * 8 + c4 + 4]);
            #pragma unroll
            for (int nt = 0; nt < 8; nt++) {
                unsigned b0 = __float_as_uint(Vs[(ks * 8 + c4) * APAD + nt * 8 + g]);
                unsigned b1 = __float_as_uint(Vs[(ks * 8 + c4 + 4) * APAD + nt * 8 + g]);
                mma8(acc[nt], a, b0, b1);
            }
        }
    }

    float inv0 = 1.0f / l0, inv1 = 1.0f / l1;
    int qr = qt * 64 + warp * 16 + g;
    #pragma unroll
    for (int nt = 0; nt < 8; nt++) {
        size_t o = ((size_t)(b * SEQ + qr)) * DMODEL + h * HD + nt * 8 + c4 * 2;
        O[o]     = acc[nt][0] * inv0;
        O[o + 1] = acc[nt][1] * inv0;
        O[o + (size_t)8 * DMODEL]     = acc[nt][2] * inv1;
        O[o + (size_t)8 * DMODEL + 1] = acc[nt][3] * inv1;
    }
}

// ---------------- launch ----------------
extern "C" void kernel_launch(void* const* d_in, const int* in_sizes, int n_in,
                              void* d_out, int out_size) {
    const float* x     = (const float*)d_in[0];
    const float* ln1_g = (const float*)d_in[1];
    const float* ln1_b = (const float*)d_in[2];
    const float* ln2_g = (const float*)d_in[3];
    const float* ln2_b = (const float*)d_in[4];
    const float* wq    = (const float*)d_in[5];
    const float* bq    = (const float*)d_in[6];
    const float* wk    = (const float*)d_in[7];
    const float* bk    = (const float*)d_in[8];
    const float* wv    = (const float*)d_in[9];
    const float* bv    = (const float*)d_in[10];
    const float* wp    = (const float*)d_in[11];
    const float* bp    = (const float*)d_in[12];
    const float* ln3_g = (const float*)d_in[13];
    const float* ln3_b = (const float*)d_in[14];
    const float* w1    = (const float*)d_in[15];
    const float* b1    = (const float*)d_in[16];
    const float* w2    = (const float*)d_in[17];
    const float* b2    = (const float*)d_in[18];
    float* out = (float*)d_out;

    float *xn, *q, *k, *v, *ctx, *y1, *ff;
    cudaGetSymbolAddress((void**)&xn,  g_xn);
    cudaGetSymbolAddress((void**)&q,   g_q);
    cudaGetSymbolAddress((void**)&k,   g_k);
    cudaGetSymbolAddress((void**)&v,   g_v);
    cudaGetSymbolAddress((void**)&ctx, g_ctx);
    cudaGetSymbolAddress((void**)&y1,  g_y1);
    cudaGetSymbolAddress((void**)&ff,  g_ff);

    cudaFuncSetAttribute(attn_kernel,
                         cudaFuncAttributeMaxDynamicSharedMemorySize, ATTN_SMEM);

    // 1. double pre-norm
    ln_double_kernel<<<MROWS, 256>>>(x, ln1_g, ln1_b, ln2_g, ln2_b, xn);

    // 2-4. Q, K, V projections
    dim3 gqkv(DMODEL / 128, MROWS / 128);
    gemm_tf32_kernel<<<gqkv, 256>>>(xn, wq, bq, nullptr, q, MROWS, DMODEL, DMODEL, 0);
    gemm_tf32_kernel<<<gqkv, 256>>>(xn, wk, bk, nullptr, k, MROWS, DMODEL, DMODEL, 0);
    gemm_tf32_kernel<<<gqkv, 256>>>(xn, wv, bv, nullptr, v, MROWS, DMODEL, DMODEL, 0);

    // 5. attention
    attn_kernel<<<dim3(BATCH * NHEAD, SEQ / 64), 128, ATTN_SMEM>>>(q, k, v, ctx);

    // 6. output projection + residual
    gemm_tf32_kernel<<<gqkv, 256>>>(ctx, wp, bp, x, y1, MROWS, DMODEL, DMODEL, 0);

    // 7. ffn pre-norm (reuse xn)
    ln_single_kernel<<<MROWS, 256>>>(y1, ln3_g, ln3_b, xn);

    // 8. FFN
    gemm_tf32_kernel<<<dim3(FFDIM / 128, MROWS / 128), 256>>>(
        xn, w1, b1, nullptr, ff, MROWS, FFDIM, DMODEL, 1);
    gemm_tf32_kernel<<<gqkv, 256>>>(ff, w2, b2, y1, out, MROWS, DMODEL, FFDIM, 0);
}